// round 13
// baseline (speedup 1.0000x reference)
#include <cuda_runtime.h>
#include <cuda_bf16.h>
#include <cstdint>
#include <cstddef>

// ---------------------------------------------------------------------------
// QLoRABigNet via int8 double-digit IMMA (Ozaki-style split).
// y = x @ W_eff^T + bias (+relu/+residual/LN), W_eff = dequant_int4 + B@A.
// x ~= sx*(x1 + x2/256), w ~= sw*(w1 + w2/256)  (per-row scales, int8 digits)
// y ~= sx*sw*(S(x1w1) + [S(x1w2)+S(x2w1)]/256)   (x2w2 dropped, ~8e-5)
// GEMM: mma.m16n8k32.s8 (2x MACs/instr vs bf16), CTA 128x64, 8 warps of
// 32x32, K-chunk 32, 4-stage mbarrier ring (validated R9/R11), 2 CTAs/SM.
// ---------------------------------------------------------------------------

#define NL    18
#define DIMV  1024
#define BV    32768
#define NGRP  64

#define TM 128
#define TN 64
#define KC32 32
#define NC (DIMV / KC32)         // 32 chunks
#define NSTAGE 4
#define NTHR 256

#define ROWB 48                  // 32B data + 16B pad, conflict-free ldsm
#define OFF_AX1 0
#define OFF_AX2 6144             // 128*48
#define OFF_BW1 12288
#define OFF_BW2 15360            // + 64*48
#define STAGE_BYTES 18432
#define MB_BASE (NSTAGE * STAGE_BYTES)      // 73728
#define SMEM_TOTAL (MB_BASE + 128)          // 73856 -> 2 CTAs/SM

// ---- scratch (device globals: allocation-free contract) --------------------
__device__ signed char g_wq1[(size_t)NL * DIMV * DIMV];
__device__ signed char g_wq2[(size_t)NL * DIMV * DIMV];
__device__ float       g_sw[(size_t)NL * DIMV];
__device__ signed char g_xq1[(size_t)BV * DIMV];
__device__ signed char g_xq2[(size_t)BV * DIMV];
__device__ float       g_sx[(size_t)BV];
__device__ float       g_ybuf[(size_t)BV * DIMV];   // fp32 y / W_eff temp
__device__ float       g_h[(size_t)BV * DIMV];      // fp32 residual h

// ---------------------------------------------------------------------------
// PTX helpers
// ---------------------------------------------------------------------------
__device__ __forceinline__ void ldsm4(uint32_t* r, uint32_t a) {
    asm volatile("ldmatrix.sync.aligned.m8n8.x4.shared.b16 {%0,%1,%2,%3}, [%4];\n"
                 : "=r"(r[0]), "=r"(r[1]), "=r"(r[2]), "=r"(r[3]) : "r"(a));
}
__device__ __forceinline__ void imma16832(int* c, const uint32_t* a, const uint32_t* b) {
    asm volatile(
        "mma.sync.aligned.m16n8k32.row.col.s32.s8.s8.s32 "
        "{%0,%1,%2,%3}, {%4,%5,%6,%7}, {%8,%9}, {%0,%1,%2,%3};\n"
        : "+r"(c[0]), "+r"(c[1]), "+r"(c[2]), "+r"(c[3])
        : "r"(a[0]), "r"(a[1]), "r"(a[2]), "r"(a[3]), "r"(b[0]), "r"(b[1]));
}
__device__ __forceinline__ void cpa16(uint32_t dst, const void* src) {
    asm volatile("cp.async.cg.shared.global [%0], [%1], 16;" :: "r"(dst), "l"(src));
}
__device__ __forceinline__ void mbar_init(uint32_t addr, uint32_t cnt) {
    asm volatile("mbarrier.init.shared.b64 [%0], %1;" :: "r"(addr), "r"(cnt) : "memory");
}
__device__ __forceinline__ void mbar_arrive(uint32_t addr) {
    asm volatile("mbarrier.arrive.shared.b64 _, [%0];" :: "r"(addr) : "memory");
}
__device__ __forceinline__ void cp_arrive_noinc(uint32_t addr) {
    asm volatile("cp.async.mbarrier.arrive.noinc.shared.b64 [%0];" :: "r"(addr) : "memory");
}
__device__ __forceinline__ void mbar_wait(uint32_t addr, uint32_t parity) {
    asm volatile(
        "{\n .reg .pred P;\n"
        "W%=:\n mbarrier.try_wait.parity.acquire.cta.shared::cta.b64 P, [%0], %1, 0x989680;\n"
        " @P bra D%=;\n bra W%=;\nD%=:\n}"
        :: "r"(addr), "r"(parity) : "memory");
}
__device__ __forceinline__ void mbar_wait_relaxed(uint32_t addr, uint32_t parity) {
    asm volatile(
        "{\n .reg .pred P;\n"
        "W%=:\n mbarrier.try_wait.parity.relaxed.cta.shared::cta.b64 P, [%0], %1, 0x989680;\n"
        " @P bra D%=;\n bra W%=;\nD%=:\n}"
        :: "r"(addr), "r"(parity) : "memory");
}

// ---------------------------------------------------------------------------
// Prepass 1: W_eff = qw*scale + B@A -> fp32 into wtmp (=g_ybuf, free until L0)
// ---------------------------------------------------------------------------
__global__ __launch_bounds__(256) void prep_w_kernel(
    const int* __restrict__ qw, const float* __restrict__ sc,
    const float* __restrict__ la, const float* __restrict__ lb,
    float* __restrict__ wtmp)
{
    int l  = blockIdx.z;
    int o0 = blockIdx.y * 64;
    int k0 = blockIdx.x * 64;
    int tid = threadIdx.x;

    __shared__ float sLb[64][32];
    __shared__ float sLa[32][64];

    const float* lbp = lb + (size_t)l * DIMV * 32;
    const float* lap = la + (size_t)l * 32 * DIMV;

#pragma unroll
    for (int i = 0; i < 8; i++) {
        int off = tid + i * 256;
        int o = off >> 5, r = off & 31;
        sLb[o][r] = lbp[(size_t)(o0 + o) * 32 + r];
        int r2 = off >> 6, k = off & 63;
        sLa[r2][k] = lap[(size_t)r2 * DIMV + k0 + k];
    }
    __syncthreads();

    int to = tid >> 4, tk = tid & 15;
    float m[4][4];
#pragma unroll
    for (int i = 0; i < 4; i++)
#pragma unroll
        for (int j = 0; j < 4; j++) m[i][j] = 0.f;

#pragma unroll 8
    for (int r = 0; r < 32; r++) {
        float av[4], bv[4];
#pragma unroll
        for (int j = 0; j < 4; j++) av[j] = sLa[r][tk * 4 + j];
#pragma unroll
        for (int i = 0; i < 4; i++) bv[i] = sLb[to * 4 + i][r];
#pragma unroll
        for (int i = 0; i < 4; i++)
#pragma unroll
            for (int j = 0; j < 4; j++) m[i][j] += bv[i] * av[j];
    }

#pragma unroll
    for (int i = 0; i < 4; i++) {
        int o = o0 + to * 4 + i;
        const int*   qrow = qw + ((size_t)l * DIMV + o) * DIMV + k0;
        const float* srow = sc + ((size_t)l * DIMV + o) * NGRP;
#pragma unroll
        for (int j = 0; j < 4; j++) {
            int k = k0 + tk * 4 + j;
            wtmp[((size_t)l * DIMV + o) * DIMV + k] =
                (float)qrow[tk * 4 + j] * srow[k >> 4] + m[i][j];
        }
    }
}

// ---------------------------------------------------------------------------
// Row quantizer core: rowmax -> sx, digits d1 = rint(v/sx), d2 = rint(res*256)
// ---------------------------------------------------------------------------
__device__ __forceinline__ float block_absmax(const float* v, float* red,
                                              int tid) {
    float m = fmaxf(fmaxf(fabsf(v[0]), fabsf(v[1])),
                    fmaxf(fabsf(v[2]), fabsf(v[3])));
#pragma unroll
    for (int o = 16; o > 0; o >>= 1)
        m = fmaxf(m, __shfl_xor_sync(0xffffffffu, m, o));
    int w = tid >> 5, ln = tid & 31;
    if (ln == 0) red[w] = m;
    __syncthreads();
    float t = 0.f;
#pragma unroll
    for (int i = 0; i < 8; i++) t = fmaxf(t, red[i]);
    return t;
}

__device__ __forceinline__ void quant_pair(float v, float inv,
                                           signed char* q1, signed char* q2) {
    float f = v * inv;
    float i1 = rintf(f);
    float i2 = rintf((f - i1) * 256.0f);
    i2 = fminf(fmaxf(i2, -127.f), 127.f);
    *q1 = (signed char)(int)i1;
    *q2 = (signed char)(int)i2;
}

// quantize rows of a fp32 matrix (activations or weights)
__global__ __launch_bounds__(256) void quant_rows_kernel(
    const float* __restrict__ t, signed char* __restrict__ q1,
    signed char* __restrict__ q2, float* __restrict__ srow)
{
    int row = blockIdx.x, tid = threadIdx.x;
    const float* tr = t + (size_t)row * DIMV;
    float v[4];
#pragma unroll
    for (int i = 0; i < 4; i++) v[i] = tr[tid + 256 * i];

    __shared__ float red[8];
    float m = block_absmax(v, red, tid);
    float inv = (m > 0.f) ? (127.0f / m) : 0.f;
    if (tid == 0) srow[row] = m * (1.0f / 127.0f);

#pragma unroll
    for (int i = 0; i < 4; i++) {
        size_t idx = (size_t)row * DIMV + tid + 256 * i;
        signed char a, b;
        quant_pair(v[i], inv, &a, &b);
        q1[idx] = a; q2[idx] = b;
    }
}

// LayerNorm + quantize + fp32 h out (residual source)
__global__ __launch_bounds__(256) void ln_quant_kernel(
    const float* __restrict__ t, const float* __restrict__ g,
    const float* __restrict__ bb, float* __restrict__ hout,
    signed char* __restrict__ q1, signed char* __restrict__ q2,
    float* __restrict__ srow)
{
    int row = blockIdx.x, tid = threadIdx.x;
    const float* tr = t + (size_t)row * DIMV;
    float v[4];
#pragma unroll
    for (int i = 0; i < 4; i++) v[i] = tr[tid + 256 * i];

    float s = v[0] + v[1] + v[2] + v[3];
#pragma unroll
    for (int o = 16; o > 0; o >>= 1) s += __shfl_xor_sync(0xffffffffu, s, o);
    __shared__ float red[8];
    int w = tid >> 5, ln = tid & 31;
    if (ln == 0) red[w] = s;
    __syncthreads();
    float tot = 0.f;
#pragma unroll
    for (int i = 0; i < 8; i++) tot += red[i];
    float mu = tot * (1.0f / 1024.0f);

    float sq = 0.f;
#pragma unroll
    for (int i = 0; i < 4; i++) { float d = v[i] - mu; sq += d * d; }
#pragma unroll
    for (int o = 16; o > 0; o >>= 1) sq += __shfl_xor_sync(0xffffffffu, sq, o);
    __syncthreads();
    if (ln == 0) red[w] = sq;
    __syncthreads();
    float vtot = 0.f;
#pragma unroll
    for (int i = 0; i < 8; i++) vtot += red[i];
    float rs = rsqrtf(vtot * (1.0f / 1024.0f) + 1e-5f);

    float o4[4];
#pragma unroll
    for (int i = 0; i < 4; i++) {
        int col = tid + 256 * i;
        o4[i] = (v[i] - mu) * rs * g[col] + bb[col];
        hout[(size_t)row * DIMV + col] = o4[i];
    }
    __syncthreads();
    float m = block_absmax(o4, red, tid);
    float inv = (m > 0.f) ? (127.0f / m) : 0.f;
    if (tid == 0) srow[row] = m * (1.0f / 127.0f);
#pragma unroll
    for (int i = 0; i < 4; i++) {
        size_t idx = (size_t)row * DIMV + tid + 256 * i;
        signed char a, b;
        quant_pair(o4[i], inv, &a, &b);
        q1[idx] = a; q2[idx] = b;
    }
}

// ---------------------------------------------------------------------------
// int8 GEMM: C[BV,DIMV] = X @ W^T. grid (16, 256), 256 thr, 8 warps (4x2),
// warp tile 32x32, mma.m16n8k32.s8, 4-stage mbarrier ring, 2 CTAs/SM.
// mode 0: fout = relu(y + bias)      (fp32; quantized by follow-up kernel)
// mode 1: fout = y + bias + hinf     (fp32 residual add)
// ---------------------------------------------------------------------------
__global__ __launch_bounds__(NTHR, 2) void gemm_kernel(
    const signed char* __restrict__ Xq1, const signed char* __restrict__ Xq2,
    const float* __restrict__ sx,
    const signed char* __restrict__ Wq1, const signed char* __restrict__ Wq2,
    const float* __restrict__ sw,
    const float* __restrict__ bias, int mode,
    const float* __restrict__ hinf, float* __restrict__ fout)
{
    extern __shared__ __align__(128) char smem[];
    const uint32_t sb = (uint32_t)__cvta_generic_to_shared(smem);

    const int tid = threadIdx.x, warp = tid >> 5, lane = tid & 31;
    const int wm = warp >> 1, wn = warp & 1;      // 4 x 2 warps, 32x32 tile
    const int m0 = blockIdx.y * TM, n0 = blockIdx.x * TN;

    if (tid == 0) {
#pragma unroll
        for (int s = 0; s < NSTAGE; s++) {
            mbar_init(sb + MB_BASE + s * 16, NTHR);
            mbar_init(sb + MB_BASE + s * 16 + 8, 8);
        }
    }
    __syncthreads();

    // producer layout: A 128 rows x 2 segs (both digits per thread);
    // B 64 rows x 2 segs x 2 digits (one per thread)
    const int arow = tid >> 1, aseg = tid & 1;
    const uint32_t aoff = (uint32_t)(arow * ROWB + aseg * 16);
    const signed char* pX1 = Xq1 + (size_t)(m0 + arow) * DIMV + aseg * 16;
    const signed char* pX2 = Xq2 + (size_t)(m0 + arow) * DIMV + aseg * 16;
    const int bdig = tid >> 7, brow = (tid >> 1) & 63, bseg = tid & 1;
    const signed char* pB = (bdig ? Wq2 : Wq1) + (size_t)(n0 + brow) * DIMV + bseg * 16;
    const uint32_t bsm = (uint32_t)((bdig ? OFF_BW2 : OFF_BW1) + brow * ROWB + bseg * 16);

#define PRODUCE(sidx, cidx)                                                    \
    do {                                                                       \
        const uint32_t _st = sb + (uint32_t)(sidx) * STAGE_BYTES;              \
        const int _k = (cidx) * KC32;                                          \
        cpa16(_st + OFF_AX1 + aoff, pX1 + _k);                                 \
        cpa16(_st + OFF_AX2 + aoff, pX2 + _k);                                 \
        cpa16(_st + bsm, pB + _k);                                             \
        cp_arrive_noinc(sb + MB_BASE + (uint32_t)(sidx) * 16);                 \
    } while (0)

    // ldmatrix lane addressing (int8 rows of 32B, 16B halves)
    const uint32_t a_base = (uint32_t)((wm * 32 + (lane & 15)) * ROWB
                                       + ((lane >> 4) << 4));
    const uint32_t b_base = (uint32_t)((wn * 32 + (lane & 7) + (((lane >> 4) & 1) << 3)) * ROWB
                                       + (((lane >> 3) & 1) << 4));

    PRODUCE(0, 0);
    PRODUCE(1, 1);

    int hh[2][4][4], cr[2][4][4];
#pragma unroll
    for (int i = 0; i < 2; i++)
#pragma unroll
        for (int j = 0; j < 4; j++)
#pragma unroll
            for (int q = 0; q < 4; q++) { hh[i][j][q] = 0; cr[i][j][q] = 0; }

#pragma unroll 4
    for (int c = 0; c < NC; ++c) {
        const int pc = c + 2;
        if (pc < NC) {
            const int ps = pc & 3, pj = pc >> 2;
            if (pj > 0)
                mbar_wait_relaxed(sb + MB_BASE + (uint32_t)ps * 16 + 8, (pj - 1) & 1);
            PRODUCE(ps, pc);
        }

        const int s = c & 3, j = c >> 2;
        mbar_wait(sb + MB_BASE + (uint32_t)s * 16, j & 1);
        const uint32_t st = sb + (uint32_t)s * STAGE_BYTES;

        // A fragments: [digit][mf][4]
        uint32_t xf[2][2][4];
#pragma unroll
        for (int mf = 0; mf < 2; mf++) {
            ldsm4(xf[0][mf], st + OFF_AX1 + a_base + (uint32_t)(mf * 16 * ROWB));
            ldsm4(xf[1][mf], st + OFF_AX2 + a_base + (uint32_t)(mf * 16 * ROWB));
        }
        // B fragments: [digit][pair of n-tiles][4] (regs 0,1 = tile 2p; 2,3 = 2p+1)
        uint32_t wf[2][2][4];
#pragma unroll
        for (int p = 0; p < 2; p++) {
            ldsm4(wf[0][p], st + OFF_BW1 + b_base + (uint32_t)(p * 16 * ROWB));
            ldsm4(wf[1][p], st + OFF_BW2 + b_base + (uint32_t)(p * 16 * ROWB));
        }
        if (lane == 0)
            mbar_arrive(sb + MB_BASE + (uint32_t)s * 16 + 8);

        // pass 1: x1*w1 -> hh ; pass 2: x1*w2 -> cr ; pass 3: x2*w1 -> cr
#pragma unroll
        for (int mf = 0; mf < 2; mf++)
#pragma unroll
            for (int nf = 0; nf < 4; nf++)
                imma16832(hh[mf][nf], xf[0][mf], &wf[0][nf >> 1][2 * (nf & 1)]);
#pragma unroll
        for (int mf = 0; mf < 2; mf++)
#pragma unroll
            for (int nf = 0; nf < 4; nf++)
                imma16832(cr[mf][nf], xf[0][mf], &wf[1][nf >> 1][2 * (nf & 1)]);
#pragma unroll
        for (int mf = 0; mf < 2; mf++)
#pragma unroll
            for (int nf = 0; nf < 4; nf++)
                imma16832(cr[mf][nf], xf[1][mf], &wf[0][nf >> 1][2 * (nf & 1)]);
    }
#undef PRODUCE

    // epilogue: y = sx*sw*(hh + cr/256) + bias (+relu | +residual)
#pragma unroll
    for (int mf = 0; mf < 2; mf++) {
        int r0 = m0 + wm * 32 + mf * 16 + (lane >> 2);
        int r1 = r0 + 8;
        float s0 = sx[r0], s1 = sx[r1];
#pragma unroll
        for (int nf = 0; nf < 4; nf++) {
            int n = n0 + wn * 32 + nf * 8 + 2 * (lane & 3);
            float w0 = sw[n], w1 = sw[n + 1];
            float b0 = bias[n], b1 = bias[n + 1];
            const int* h = hh[mf][nf];
            const int* cc = cr[mf][nf];
            float y00 = s0 * w0 * ((float)h[0] + (float)cc[0] * (1.f / 256.f)) + b0;
            float y01 = s0 * w1 * ((float)h[1] + (float)cc[1] * (1.f / 256.f)) + b1;
            float y10 = s1 * w0 * ((float)h[2] + (float)cc[2] * (1.f / 256.f)) + b0;
            float y11 = s1 * w1 * ((float)h[3] + (float)cc[3] * (1.f / 256.f)) + b1;
            size_t o0 = (size_t)r0 * DIMV + n;
            size_t o1 = (size_t)r1 * DIMV + n;
            if (mode == 0) {
                float2 a; a.x = fmaxf(y00, 0.f); a.y = fmaxf(y01, 0.f);
                float2 b; b.x = fmaxf(y10, 0.f); b.y = fmaxf(y11, 0.f);
                *(float2*)(fout + o0) = a;
                *(float2*)(fout + o1) = b;
            } else {
                float2 hv0 = *(const float2*)(hinf + o0);
                float2 hv1 = *(const float2*)(hinf + o1);
                float2 a; a.x = y00 + hv0.x; a.y = y01 + hv0.y;
                float2 b; b.x = y10 + hv1.x; b.y = y11 + hv1.y;
                *(float2*)(fout + o0) = a;
                *(float2*)(fout + o1) = b;
            }
        }
    }
}

// ---------------------------------------------------------------------------
// Host
// ---------------------------------------------------------------------------
extern "C" void kernel_launch(void* const* d_in, const int* in_sizes, int n_in,
                              void* d_out, int out_size)
{
    const float* x      = (const float*)d_in[0];
    const int*   qw     = (const int*)d_in[1];
    const float* scales = (const float*)d_in[2];
    const float* bias   = (const float*)d_in[3];
    const float* la     = (const float*)d_in[4];
    const float* lb     = (const float*)d_in[5];
    const float* lng    = (const float*)d_in[6];
    const float* lnb    = (const float*)d_in[7];
    float* out = (float*)d_out;

    void* p;
    cudaGetSymbolAddress(&p, g_wq1);  signed char* Wq1 = (signed char*)p;
    cudaGetSymbolAddress(&p, g_wq2);  signed char* Wq2 = (signed char*)p;
    cudaGetSymbolAddress(&p, g_sw);   float* Sw = (float*)p;
    cudaGetSymbolAddress(&p, g_xq1);  signed char* Xq1 = (signed char*)p;
    cudaGetSymbolAddress(&p, g_xq2);  signed char* Xq2 = (signed char*)p;
    cudaGetSymbolAddress(&p, g_sx);   float* Sx = (float*)p;
    cudaGetSymbolAddress(&p, g_ybuf); float* Ybuf = (float*)p;
    cudaGetSymbolAddress(&p, g_h);    float* Hbuf = (float*)p;

    cudaFuncSetAttribute(gemm_kernel,
                         cudaFuncAttributeMaxDynamicSharedMemorySize, SMEM_TOTAL);

    // W_eff fp32 into Ybuf (temp), then quantize to digit pairs
    prep_w_kernel<<<dim3(16, 16, NL), 256>>>(qw, scales, la, lb, Ybuf);
    quant_rows_kernel<<<NL * DIMV, 256>>>(Ybuf, Wq1, Wq2, Sw);
    // initial activation quantization
    quant_rows_kernel<<<BV, 256>>>(x, Xq1, Xq2, Sx);

    for (int l = 0; l < NL; l++) {
        const signed char* wq1 = Wq1 + (size_t)l * DIMV * DIMV;
        const signed char* wq2 = Wq2 + (size_t)l * DIMV * DIMV;
        const float* swl = Sw + (size_t)l * DIMV;
        const float* bl  = bias + (size_t)l * DIMV;
        const int j = l % 3;

        if (j != 2) {
            gemm_kernel<<<dim3(DIMV / TN, BV / TM), NTHR, SMEM_TOTAL>>>(
                Xq1, Xq2, Sx, wq1, wq2, swl, bl, 0, nullptr, Ybuf);
            quant_rows_kernel<<<BV, 256>>>(Ybuf, Xq1, Xq2, Sx);
        } else {
            const float* hinf = (l == 2) ? x : Hbuf;
            float* fo = (l == NL - 1) ? out : Ybuf;
            gemm_kernel<<<dim3(DIMV / TN, BV / TM), NTHR, SMEM_TOTAL>>>(
                Xq1, Xq2, Sx, wq1, wq2, swl, bl, 1, hinf, fo);
            if (l != NL - 1) {
                int blk = l / 3;
                ln_quant_kernel<<<BV, 256>>>(Ybuf, lng + (size_t)blk * DIMV,
                                             lnb + (size_t)blk * DIMV, Hbuf,
                                             Xq1, Xq2, Sx);
            }
        }
    }
}

// round 15
// speedup vs baseline: 2.0108x; 2.0108x over previous
#include <cuda_runtime.h>
#include <cuda_bf16.h>
#include <cstdint>
#include <cstddef>

// ---------------------------------------------------------------------------
// QLoRABigNet, mma.sync bf16 path (tcgen05 unavailable at compute_103 target;
// int8 IMMA measured 4-5x de-rated on sm_103a in R13 -> bf16 HMMA is optimal).
// 18 layers of y = x @ W_eff^T + bias (+relu / +residual / LN).
// W_eff = dequant_int4 + lora_b@lora_a precomputed; split-bf16 3-MMA numerics.
// R14: K=32 chunks, 3-stage mbarrier ring, produce-ahead-2 (drift = 64K).
//      Packed 64B rows + seg-XOR swizzle (seg^=(row>>1)&3) -> stage 32KB,
//      total 98KB (2 CTAs/SM kept), conflict-free ldsm + cp.async.
// ---------------------------------------------------------------------------

#define NL    18
#define DIMV  1024
#define BV    32768
#define NGRP  64

#define TM 128
#define TN 128
#define KC32 32
#define NC (DIMV / KC32)         // 32 chunks
#define NSTAGE 3
#define NTHR 256

#define OFF_AHI 0
#define OFF_ALO 8192             // 128 rows * 64B
#define OFF_BHI 16384
#define OFF_BLO 24576
#define STAGE_BYTES 32768
#define MB_BASE (NSTAGE * STAGE_BYTES)      // 98304
#define SMEM_TOTAL (MB_BASE + 128)          // 98432 -> 2 CTAs/SM

// ---- scratch (device globals: allocation-free contract) --------------------
__device__ __nv_bfloat16 g_Whi[(size_t)NL * DIMV * DIMV];
__device__ __nv_bfloat16 g_Wlo[(size_t)NL * DIMV * DIMV];
__device__ __nv_bfloat16 g_ahi0[(size_t)BV * DIMV];
__device__ __nv_bfloat16 g_alo0[(size_t)BV * DIMV];
__device__ __nv_bfloat16 g_ahi1[(size_t)BV * DIMV];
__device__ __nv_bfloat16 g_alo1[(size_t)BV * DIMV];
__device__ float         g_ybuf[(size_t)BV * DIMV];
__device__ float         g_h[(size_t)BV * DIMV];   // carved: Hhi | Hlo (bf16)

// ---------------------------------------------------------------------------
// PTX helpers
// ---------------------------------------------------------------------------
__device__ __forceinline__ void ldsm4(uint32_t* r, uint32_t a) {
    asm volatile("ldmatrix.sync.aligned.m8n8.x4.shared.b16 {%0,%1,%2,%3}, [%4];\n"
                 : "=r"(r[0]), "=r"(r[1]), "=r"(r[2]), "=r"(r[3]) : "r"(a));
}
__device__ __forceinline__ void mma16816(float* c, const uint32_t* a, const uint32_t* b) {
    asm volatile(
        "mma.sync.aligned.m16n8k16.row.col.f32.bf16.bf16.f32 "
        "{%0,%1,%2,%3}, {%4,%5,%6,%7}, {%8,%9}, {%0,%1,%2,%3};\n"
        : "+f"(c[0]), "+f"(c[1]), "+f"(c[2]), "+f"(c[3])
        : "r"(a[0]), "r"(a[1]), "r"(a[2]), "r"(a[3]), "r"(b[0]), "r"(b[1]));
}
__device__ __forceinline__ void cpa16(uint32_t dst, const void* src) {
    asm volatile("cp.async.cg.shared.global [%0], [%1], 16;" :: "r"(dst), "l"(src));
}
__device__ __forceinline__ void mbar_init(uint32_t addr, uint32_t cnt) {
    asm volatile("mbarrier.init.shared.b64 [%0], %1;" :: "r"(addr), "r"(cnt) : "memory");
}
__device__ __forceinline__ void mbar_arrive(uint32_t addr) {
    asm volatile("mbarrier.arrive.shared.b64 _, [%0];" :: "r"(addr) : "memory");
}
__device__ __forceinline__ void cp_arrive_noinc(uint32_t addr) {
    asm volatile("cp.async.mbarrier.arrive.noinc.shared.b64 [%0];" :: "r"(addr) : "memory");
}
__device__ __forceinline__ void mbar_wait(uint32_t addr, uint32_t parity) {
    asm volatile(
        "{\n .reg .pred P;\n"
        "W%=:\n mbarrier.try_wait.parity.acquire.cta.shared::cta.b64 P, [%0], %1, 0x989680;\n"
        " @P bra D%=;\n bra W%=;\nD%=:\n}"
        :: "r"(addr), "r"(parity) : "memory");
}
__device__ __forceinline__ void mbar_wait_relaxed(uint32_t addr, uint32_t parity) {
    asm volatile(
        "{\n .reg .pred P;\n"
        "W%=:\n mbarrier.try_wait.parity.relaxed.cta.shared::cta.b64 P, [%0], %1, 0x989680;\n"
        " @P bra D%=;\n bra W%=;\nD%=:\n}"
        :: "r"(addr), "r"(parity) : "memory");
}

// ---------------------------------------------------------------------------
// Prepass: W_eff = qw*scale + B@A, split bf16 hi/lo. (validated R3/R5-R12)
// ---------------------------------------------------------------------------
__global__ __launch_bounds__(256) void prep_w_kernel(
    const int* __restrict__ qw, const float* __restrict__ sc,
    const float* __restrict__ la, const float* __restrict__ lb,
    __nv_bfloat16* __restrict__ Whi, __nv_bfloat16* __restrict__ Wlo)
{
    int l  = blockIdx.z;
    int o0 = blockIdx.y * 64;
    int k0 = blockIdx.x * 64;
    int tid = threadIdx.x;

    __shared__ float sLb[64][32];
    __shared__ float sLa[32][64];

    const float* lbp = lb + (size_t)l * DIMV * 32;
    const float* lap = la + (size_t)l * 32 * DIMV;

#pragma unroll
    for (int i = 0; i < 8; i++) {
        int off = tid + i * 256;
        int o = off >> 5, r = off & 31;
        sLb[o][r] = lbp[(size_t)(o0 + o) * 32 + r];
        int r2 = off >> 6, k = off & 63;
        sLa[r2][k] = lap[(size_t)r2 * DIMV + k0 + k];
    }
    __syncthreads();

    int to = tid >> 4, tk = tid & 15;
    float m[4][4];
#pragma unroll
    for (int i = 0; i < 4; i++)
#pragma unroll
        for (int j = 0; j < 4; j++) m[i][j] = 0.f;

#pragma unroll 8
    for (int r = 0; r < 32; r++) {
        float av[4], bv[4];
#pragma unroll
        for (int j = 0; j < 4; j++) av[j] = sLa[r][tk * 4 + j];
#pragma unroll
        for (int i = 0; i < 4; i++) bv[i] = sLb[to * 4 + i][r];
#pragma unroll
        for (int i = 0; i < 4; i++)
#pragma unroll
            for (int j = 0; j < 4; j++) m[i][j] += bv[i] * av[j];
    }

#pragma unroll
    for (int i = 0; i < 4; i++) {
        int o = o0 + to * 4 + i;
        const int*   qrow = qw + ((size_t)l * DIMV + o) * DIMV + k0;
        const float* srow = sc + ((size_t)l * DIMV + o) * NGRP;
#pragma unroll
        for (int j = 0; j < 4; j++) {
            int k = k0 + tk * 4 + j;
            float wv = (float)qrow[tk * 4 + j] * srow[k >> 4] + m[i][j];
            size_t idx = ((size_t)l * DIMV + o) * DIMV + k;
            __nv_bfloat16 h = __float2bfloat16(wv);
            Whi[idx] = h;
            Wlo[idx] = __float2bfloat16(wv - __bfloat162float(h));
        }
    }
}

__global__ __launch_bounds__(256) void split_x_kernel(
    const float* __restrict__ x, __nv_bfloat16* __restrict__ hi,
    __nv_bfloat16* __restrict__ lo)
{
    size_t i = (size_t)blockIdx.x * 256 + threadIdx.x;
    float v = x[i];
    __nv_bfloat16 h = __float2bfloat16(v);
    hi[i] = h;
    lo[i] = __float2bfloat16(v - __bfloat162float(h));
}

// ---------------------------------------------------------------------------
// GEMM: C[BV,DIMV] = X @ W^T. grid (8, 256), 256 threads, 8 warps (2x4),
// warp tile 64x32. 3-stage mbarrier ring over K=32 chunks, ahead-2, 2 CTAs/SM.
// Packed 64B rows with seg swizzle: addr = row*64 + ((seg ^ ((row>>1)&3))<<4).
// mode 0: out = relu(acc+bias) -> bf16 hi/lo pair
// mode 1: out = acc+bias+res -> fp32 (res = hinf fp32 or hi+lo bf16 pair)
// ---------------------------------------------------------------------------
__global__ __launch_bounds__(NTHR, 2) void gemm_kernel(
    const __nv_bfloat16* __restrict__ Xhi, const __nv_bfloat16* __restrict__ Xlo,
    const __nv_bfloat16* __restrict__ Whi, const __nv_bfloat16* __restrict__ Wlo,
    const float* __restrict__ bias, int mode,
    const float* __restrict__ hinf,
    const __nv_bfloat16* __restrict__ hinh, const __nv_bfloat16* __restrict__ hinl,
    float* __restrict__ fout,
    __nv_bfloat16* __restrict__ Ohi, __nv_bfloat16* __restrict__ Olo)
{
    extern __shared__ __align__(128) char smem[];
    const uint32_t sb = (uint32_t)__cvta_generic_to_shared(smem);

    const int tid = threadIdx.x, warp = tid >> 5, lane = tid & 31;
    const int wm = warp >> 2, wn = warp & 3;         // 2 x 4 warp grid, 64x32 tile
    const int m0 = blockIdx.y * TM, n0 = blockIdx.x * TN;

    if (tid == 0) {
#pragma unroll
        for (int s = 0; s < NSTAGE; s++) {
            mbar_init(sb + MB_BASE + s * 16, NTHR);  // full
            mbar_init(sb + MB_BASE + s * 16 + 8, 8); // empty
        }
    }
    __syncthreads();

    // producer per-thread layout: (row0 = tid>>2, seg = tid&3) and row1 = row0+64
    const int prow = tid >> 2, pseg = tid & 3;
    const int px = (prow >> 1) & 3;                  // same for row0 and row0+64
    const uint32_t poff0 = (uint32_t)(prow * 64 + ((pseg ^ px) << 4));
    const uint32_t poff1 = poff0 + 64 * 64;
    const __nv_bfloat16* pXh = Xhi + (size_t)(m0 + prow) * DIMV + pseg * 8;
    const __nv_bfloat16* pXl = Xlo + (size_t)(m0 + prow) * DIMV + pseg * 8;
    const __nv_bfloat16* pWh = Whi + (size_t)(n0 + prow) * DIMV + pseg * 8;
    const __nv_bfloat16* pWl = Wlo + (size_t)(n0 + prow) * DIMV + pseg * 8;
    const size_t rstep = (size_t)64 * DIMV;

#define PRODUCE(sidx, cidx)                                                    \
    do {                                                                       \
        const uint32_t _st = sb + (uint32_t)(sidx) * STAGE_BYTES;              \
        const int _k = (cidx) * KC32;                                          \
        cpa16(_st + OFF_AHI + poff0, pXh + _k);                                \
        cpa16(_st + OFF_ALO + poff0, pXl + _k);                                \
        cpa16(_st + OFF_BHI + poff0, pWh + _k);                                \
        cpa16(_st + OFF_BLO + poff0, pWl + _k);                                \
        cpa16(_st + OFF_AHI + poff1, pXh + rstep + _k);                        \
        cpa16(_st + OFF_ALO + poff1, pXl + rstep + _k);                        \
        cpa16(_st + OFF_BHI + poff1, pWh + rstep + _k);                        \
        cpa16(_st + OFF_BLO + poff1, pWl + rstep + _k);                        \
        cp_arrive_noinc(sb + MB_BASE + (uint32_t)(sidx) * 16);                 \
    } while (0)

    // ldmatrix per-lane addressing with seg swizzle
    const int mi = lane >> 3, rr = lane & 7;
    const int a_row = wm * 64 + (mi & 1) * 8 + rr;
    const int s0a = mi >> 1;
    const int xa = (a_row >> 1) & 3;                 // mf-invariant (mf adds 16)
    const uint32_t a_base = (uint32_t)(a_row * 64 + ((s0a ^ (xa & 1)) << 4)
                                       + ((xa >> 1) << 5));
    const int b_row = wn * 32 + (lane & 7) + ((lane >> 4) & 1) * 8;
    const int s0b = (lane >> 3) & 1;
    const int xb = (b_row >> 1) & 3;                 // nfp-invariant
    const uint32_t b_base = (uint32_t)(b_row * 64 + ((s0b ^ (xb & 1)) << 4)
                                       + ((xb >> 1) << 5));

    // prologue: chunks 0,1 into stages 0,1 (ahead-2)
    PRODUCE(0, 0);
    PRODUCE(1, 1);

    float acc[4][4][4];
#pragma unroll
    for (int i = 0; i < 4; i++)
#pragma unroll
        for (int j = 0; j < 4; j++)
#pragma unroll
            for (int q = 0; q < 4; q++) acc[i][j][q] = 0.f;

    int cs = 0, cround = 0;      // consumer stage / fill-round of that stage
    int ps = 2, pround = 0;      // producer stage / production round

#pragma unroll 1
    for (int c = 0; c < NC; ++c) {
        // produce chunk c+2 into stage ps (gated on consumption round pround-1)
        if (c + 2 < NC) {
            if (pround > 0)
                mbar_wait_relaxed(sb + MB_BASE + (uint32_t)ps * 16 + 8,
                                  (pround - 1) & 1);
            PRODUCE(ps, c + 2);
            if (++ps == NSTAGE) { ps = 0; pround++; }
        }

        // consume chunk c from stage cs
        mbar_wait(sb + MB_BASE + (uint32_t)cs * 16, cround & 1);
        const uint32_t st = sb + (uint32_t)cs * STAGE_BYTES;

#pragma unroll
        for (int ks = 0; ks < 2; ks++) {
            const uint32_t kx = (uint32_t)(ks << 5);  // toggles 32B k16-half

            // hi batch
            uint32_t wh[8], fxh[4][4];
#pragma unroll
            for (int p = 0; p < 2; p++)
                ldsm4(wh + 4 * p, st + OFF_BHI + ((b_base + (uint32_t)(p * 1024)) ^ kx));
#pragma unroll
            for (int mf = 0; mf < 4; mf++)
                ldsm4(fxh[mf], st + OFF_AHI + ((a_base + (uint32_t)(mf * 1024)) ^ kx));

            // pass 1 (hi x hi) overlaps the lo-batch LDSM latency
#pragma unroll
            for (int mf = 0; mf < 4; mf++)
#pragma unroll
                for (int nf = 0; nf < 4; nf++)
                    mma16816(acc[mf][nf], fxh[mf], wh + 2 * nf);

            // lo batch
            uint32_t wl[8], fxl[4][4];
#pragma unroll
            for (int p = 0; p < 2; p++)
                ldsm4(wl + 4 * p, st + OFF_BLO + ((b_base + (uint32_t)(p * 1024)) ^ kx));
#pragma unroll
            for (int mf = 0; mf < 4; mf++)
                ldsm4(fxl[mf], st + OFF_ALO + ((a_base + (uint32_t)(mf * 1024)) ^ kx));

            if (ks == 1 && lane == 0)
                mbar_arrive(sb + MB_BASE + (uint32_t)cs * 16 + 8);

            // passes 2 and 3
#pragma unroll
            for (int mf = 0; mf < 4; mf++)
#pragma unroll
                for (int nf = 0; nf < 4; nf++)
                    mma16816(acc[mf][nf], fxl[mf], wh + 2 * nf);
#pragma unroll
            for (int mf = 0; mf < 4; mf++)
#pragma unroll
                for (int nf = 0; nf < 4; nf++)
                    mma16816(acc[mf][nf], fxh[mf], wl + 2 * nf);
        }
        if (++cs == NSTAGE) { cs = 0; cround++; }
    }
#undef PRODUCE

    // epilogue
#pragma unroll
    for (int mf = 0; mf < 4; mf++) {
#pragma unroll
        for (int nf = 0; nf < 4; nf++) {
            const float* c = acc[mf][nf];
            int row0 = m0 + wm * 64 + mf * 16 + (lane >> 2);
            int row1 = row0 + 8;
            int n = n0 + wn * 32 + nf * 8 + 2 * (lane & 3);
            float bn0 = bias[n], bn1 = bias[n + 1];
            size_t o0 = (size_t)row0 * DIMV + n;
            size_t o1 = (size_t)row1 * DIMV + n;
            if (mode == 0) {
                float v00 = fmaxf(c[0] + bn0, 0.f), v01 = fmaxf(c[1] + bn1, 0.f);
                float v10 = fmaxf(c[2] + bn0, 0.f), v11 = fmaxf(c[3] + bn1, 0.f);
                __nv_bfloat162 h2, l2;
                h2.x = __float2bfloat16(v00); l2.x = __float2bfloat16(v00 - __bfloat162float(h2.x));
                h2.y = __float2bfloat16(v01); l2.y = __float2bfloat16(v01 - __bfloat162float(h2.y));
                *(__nv_bfloat162*)(Ohi + o0) = h2;
                *(__nv_bfloat162*)(Olo + o0) = l2;
                h2.x = __float2bfloat16(v10); l2.x = __float2bfloat16(v10 - __bfloat162float(h2.x));
                h2.y = __float2bfloat16(v11); l2.y = __float2bfloat16(v11 - __bfloat162float(h2.y));
                *(__nv_bfloat162*)(Ohi + o1) = h2;
                *(__nv_bfloat162*)(Olo + o1) = l2;
            } else {
                float2 hv0, hv1;
                if (hinf) {
                    hv0 = *(const float2*)(hinf + o0);
                    hv1 = *(const float2*)(hinf + o1);
                } else {
                    __nv_bfloat162 h0 = *(const __nv_bfloat162*)(hinh + o0);
                    __nv_bfloat162 l0 = *(const __nv_bfloat162*)(hinl + o0);
                    __nv_bfloat162 h1 = *(const __nv_bfloat162*)(hinh + o1);
                    __nv_bfloat162 l1 = *(const __nv_bfloat162*)(hinl + o1);
                    hv0.x = __bfloat162float(h0.x) + __bfloat162float(l0.x);
                    hv0.y = __bfloat162float(h0.y) + __bfloat162float(l0.y);
                    hv1.x = __bfloat162float(h1.x) + __bfloat162float(l1.x);
                    hv1.y = __bfloat162float(h1.y) + __bfloat162float(l1.y);
                }
                float2 r0v; r0v.x = c[0] + bn0 + hv0.x; r0v.y = c[1] + bn1 + hv0.y;
                float2 r1v; r1v.x = c[2] + bn0 + hv1.x; r1v.y = c[3] + bn1 + hv1.y;
                *(float2*)(fout + o0) = r0v;
                *(float2*)(fout + o1) = r1v;
            }
        }
    }
}

// ---------------------------------------------------------------------------
// LayerNorm: reads fp32 t, writes ONLY the bf16 hi/lo pair.
// ---------------------------------------------------------------------------
__global__ __launch_bounds__(256) void ln_kernel(
    const float* __restrict__ t, const float* __restrict__ g,
    const float* __restrict__ bb,
    __nv_bfloat16* __restrict__ Ohi, __nv_bfloat16* __restrict__ Olo)
{
    int row = blockIdx.x;
    int tid = threadIdx.x;
    const float* tr = t + (size_t)row * DIMV;

    float v[4];
#pragma unroll
    for (int i = 0; i < 4; i++) v[i] = tr[tid + 256 * i];

    float s = v[0] + v[1] + v[2] + v[3];
#pragma unroll
    for (int o = 16; o > 0; o >>= 1) s += __shfl_xor_sync(0xffffffffu, s, o);

    __shared__ float red[8];
    int w = tid >> 5, ln = tid & 31;
    if (ln == 0) red[w] = s;
    __syncthreads();
    float tot = 0.f;
#pragma unroll
    for (int i = 0; i < 8; i++) tot += red[i];
    float mu = tot * (1.0f / 1024.0f);

    float sq = 0.f;
#pragma unroll
    for (int i = 0; i < 4; i++) { float d = v[i] - mu; sq += d * d; }
#pragma unroll
    for (int o = 16; o > 0; o >>= 1) sq += __shfl_xor_sync(0xffffffffu, sq, o);
    __syncthreads();
    if (ln == 0) red[w] = sq;
    __syncthreads();
    float vtot = 0.f;
#pragma unroll
    for (int i = 0; i < 8; i++) vtot += red[i];
    float rs = rsqrtf(vtot * (1.0f / 1024.0f) + 1e-5f);

#pragma unroll
    for (int i = 0; i < 4; i++) {
        int col = tid + 256 * i;
        float o = (v[i] - mu) * rs * g[col] + bb[col];
        size_t idx = (size_t)row * DIMV + col;
        __nv_bfloat16 h = __float2bfloat16(o);
        Ohi[idx] = h;
        Olo[idx] = __float2bfloat16(o - __bfloat162float(h));
    }
}

// ---------------------------------------------------------------------------
// Host
// ---------------------------------------------------------------------------
extern "C" void kernel_launch(void* const* d_in, const int* in_sizes, int n_in,
                              void* d_out, int out_size)
{
    const float* x      = (const float*)d_in[0];
    const int*   qw     = (const int*)d_in[1];
    const float* scales = (const float*)d_in[2];
    const float* bias   = (const float*)d_in[3];
    const float* la     = (const float*)d_in[4];
    const float* lb     = (const float*)d_in[5];
    const float* lng    = (const float*)d_in[6];
    const float* lnb    = (const float*)d_in[7];
    float* out = (float*)d_out;

    void* p;
    cudaGetSymbolAddress(&p, g_Whi);  __nv_bfloat16* Whi  = (__nv_bfloat16*)p;
    cudaGetSymbolAddress(&p, g_Wlo);  __nv_bfloat16* Wlo  = (__nv_bfloat16*)p;
    cudaGetSymbolAddress(&p, g_ahi0); __nv_bfloat16* Ahi0 = (__nv_bfloat16*)p;
    cudaGetSymbolAddress(&p, g_alo0); __nv_bfloat16* Alo0 = (__nv_bfloat16*)p;
    cudaGetSymbolAddress(&p, g_ahi1); __nv_bfloat16* Ahi1 = (__nv_bfloat16*)p;
    cudaGetSymbolAddress(&p, g_alo1); __nv_bfloat16* Alo1 = (__nv_bfloat16*)p;
    cudaGetSymbolAddress(&p, g_ybuf); float* Ybuf = (float*)p;
    cudaGetSymbolAddress(&p, g_h);
    __nv_bfloat16* Hhi = (__nv_bfloat16*)p;
    __nv_bfloat16* Hlo = (__nv_bfloat16*)p + (size_t)BV * DIMV;

    cudaFuncSetAttribute(gemm_kernel,
                         cudaFuncAttributeMaxDynamicSharedMemorySize, SMEM_TOTAL);

    prep_w_kernel<<<dim3(16, 16, NL), 256>>>(qw, scales, la, lb, Whi, Wlo);
    split_x_kernel<<<(BV * DIMV) / 256, 256>>>(x, Hhi, Hlo);

    for (int l = 0; l < NL; l++) {
        const __nv_bfloat16* wh = Whi + (size_t)l * DIMV * DIMV;
        const __nv_bfloat16* wl = Wlo + (size_t)l * DIMV * DIMV;
        const float* bl = bias + (size_t)l * DIMV;
        const int j = l % 3;

        const __nv_bfloat16* xhi = (j == 0) ? Hhi : (j == 1 ? Ahi0 : Ahi1);
        const __nv_bfloat16* xlo = (j == 0) ? Hlo : (j == 1 ? Alo0 : Alo1);

        if (j != 2) {
            __nv_bfloat16* ohi = (j == 0) ? Ahi0 : Ahi1;
            __nv_bfloat16* olo = (j == 0) ? Alo0 : Alo1;
            gemm_kernel<<<dim3(DIMV / TN, BV / TM), NTHR, SMEM_TOTAL>>>(
                xhi, xlo, wh, wl, bl, 0,
                nullptr, nullptr, nullptr, nullptr, ohi, olo);
        } else {
            const float* hinf = (l == 2) ? x : nullptr;
            const __nv_bfloat16* hinh = (l == 2) ? nullptr : Hhi;
            const __nv_bfloat16* hinl = (l == 2) ? nullptr : Hlo;
            float* fo = (l == NL - 1) ? out : Ybuf;
            gemm_kernel<<<dim3(DIMV / TN, BV / TM), NTHR, SMEM_TOTAL>>>(
                xhi, xlo, wh, wl, bl, 1,
                hinf, hinh, hinl, fo, nullptr, nullptr);
            if (l != NL - 1) {
                int blk = l / 3;
                ln_kernel<<<BV, 256>>>(Ybuf, lng + (size_t)blk * DIMV,
                                       lnb + (size_t)blk * DIMV, Hhi, Hlo);
            }
        }
    }
}

// round 16
// speedup vs baseline: 2.1873x; 1.0878x over previous
#include <cuda_runtime.h>
#include <cuda_bf16.h>
#include <cstdint>
#include <cstddef>

// ---------------------------------------------------------------------------
// QLoRABigNet, mma.sync bf16 path (tcgen05 unavailable at compute_103 target;
// int8 IMMA 4-5x de-rated on sm_103a per R13; packed-swizzle K32 regressed
// per R15 -> champion R12 geometry retained).
// 18 layers of y = x @ W_eff^T + bias (+relu / +residual / LN).
// W_eff = dequant_int4 + lora_b@lora_a precomputed; split-bf16 3-MMA numerics.
// R16: leader-poll sync. Only warp 0 executes the mbarrier try_wait (~90cyc
//      fast-path); other warps take one __syncthreads. Stage-reuse distance 4
//      + per-chunk CTA barrier makes the empty barrier redundant -> removed.
// ---------------------------------------------------------------------------

#define NL    18
#define DIMV  1024
#define BV    32768
#define NGRP  64

#define TM 128
#define TN 128
#define KC16 16
#define NC (DIMV / KC16)         // 64 chunks
#define NSTAGE 4
#define NTHR 256

#define ROWB 48                  // 32B data + 16B pad, conflict-free ldsm
#define OFF_AHI 0
#define OFF_ALO 6144             // 128*48
#define OFF_BHI 12288
#define OFF_BLO 18432
#define STAGE_BYTES 24576
#define MB_BASE (NSTAGE * STAGE_BYTES)      // 98304
#define SMEM_TOTAL (MB_BASE + 128)          // 98432 -> 2 CTAs/SM

// ---- scratch (device globals: allocation-free contract) --------------------
__device__ __nv_bfloat16 g_Whi[(size_t)NL * DIMV * DIMV];
__device__ __nv_bfloat16 g_Wlo[(size_t)NL * DIMV * DIMV];
__device__ __nv_bfloat16 g_ahi0[(size_t)BV * DIMV];
__device__ __nv_bfloat16 g_alo0[(size_t)BV * DIMV];
__device__ __nv_bfloat16 g_ahi1[(size_t)BV * DIMV];
__device__ __nv_bfloat16 g_alo1[(size_t)BV * DIMV];
__device__ float         g_ybuf[(size_t)BV * DIMV];
__device__ float         g_h[(size_t)BV * DIMV];   // carved: Hhi | Hlo (bf16)

// ---------------------------------------------------------------------------
// PTX helpers
// ---------------------------------------------------------------------------
__device__ __forceinline__ void ldsm4(uint32_t* r, uint32_t a) {
    asm volatile("ldmatrix.sync.aligned.m8n8.x4.shared.b16 {%0,%1,%2,%3}, [%4];\n"
                 : "=r"(r[0]), "=r"(r[1]), "=r"(r[2]), "=r"(r[3]) : "r"(a));
}
__device__ __forceinline__ void mma16816(float* c, const uint32_t* a, const uint32_t* b) {
    asm volatile(
        "mma.sync.aligned.m16n8k16.row.col.f32.bf16.bf16.f32 "
        "{%0,%1,%2,%3}, {%4,%5,%6,%7}, {%8,%9}, {%0,%1,%2,%3};\n"
        : "+f"(c[0]), "+f"(c[1]), "+f"(c[2]), "+f"(c[3])
        : "r"(a[0]), "r"(a[1]), "r"(a[2]), "r"(a[3]), "r"(b[0]), "r"(b[1]));
}
__device__ __forceinline__ void cpa16(uint32_t dst, const void* src) {
    asm volatile("cp.async.cg.shared.global [%0], [%1], 16;" :: "r"(dst), "l"(src));
}
__device__ __forceinline__ void mbar_init(uint32_t addr, uint32_t cnt) {
    asm volatile("mbarrier.init.shared.b64 [%0], %1;" :: "r"(addr), "r"(cnt) : "memory");
}
__device__ __forceinline__ void cp_arrive_noinc(uint32_t addr) {
    asm volatile("cp.async.mbarrier.arrive.noinc.shared.b64 [%0];" :: "r"(addr) : "memory");
}
__device__ __forceinline__ void mbar_wait(uint32_t addr, uint32_t parity) {
    asm volatile(
        "{\n .reg .pred P;\n"
        "W%=:\n mbarrier.try_wait.parity.acquire.cta.shared::cta.b64 P, [%0], %1, 0x989680;\n"
        " @P bra D%=;\n bra W%=;\nD%=:\n}"
        :: "r"(addr), "r"(parity) : "memory");
}

// ---------------------------------------------------------------------------
// Prepass: W_eff = qw*scale + B@A, split bf16 hi/lo. (validated R3/R5-R12)
// ---------------------------------------------------------------------------
__global__ __launch_bounds__(256) void prep_w_kernel(
    const int* __restrict__ qw, const float* __restrict__ sc,
    const float* __restrict__ la, const float* __restrict__ lb,
    __nv_bfloat16* __restrict__ Whi, __nv_bfloat16* __restrict__ Wlo)
{
    int l  = blockIdx.z;
    int o0 = blockIdx.y * 64;
    int k0 = blockIdx.x * 64;
    int tid = threadIdx.x;

    __shared__ float sLb[64][32];
    __shared__ float sLa[32][64];

    const float* lbp = lb + (size_t)l * DIMV * 32;
    const float* lap = la + (size_t)l * 32 * DIMV;

#pragma unroll
    for (int i = 0; i < 8; i++) {
        int off = tid + i * 256;
        int o = off >> 5, r = off & 31;
        sLb[o][r] = lbp[(size_t)(o0 + o) * 32 + r];
        int r2 = off >> 6, k = off & 63;
        sLa[r2][k] = lap[(size_t)r2 * DIMV + k0 + k];
    }
    __syncthreads();

    int to = tid >> 4, tk = tid & 15;
    float m[4][4];
#pragma unroll
    for (int i = 0; i < 4; i++)
#pragma unroll
        for (int j = 0; j < 4; j++) m[i][j] = 0.f;

#pragma unroll 8
    for (int r = 0; r < 32; r++) {
        float av[4], bv[4];
#pragma unroll
        for (int j = 0; j < 4; j++) av[j] = sLa[r][tk * 4 + j];
#pragma unroll
        for (int i = 0; i < 4; i++) bv[i] = sLb[to * 4 + i][r];
#pragma unroll
        for (int i = 0; i < 4; i++)
#pragma unroll
            for (int j = 0; j < 4; j++) m[i][j] += bv[i] * av[j];
    }

#pragma unroll
    for (int i = 0; i < 4; i++) {
        int o = o0 + to * 4 + i;
        const int*   qrow = qw + ((size_t)l * DIMV + o) * DIMV + k0;
        const float* srow = sc + ((size_t)l * DIMV + o) * NGRP;
#pragma unroll
        for (int j = 0; j < 4; j++) {
            int k = k0 + tk * 4 + j;
            float wv = (float)qrow[tk * 4 + j] * srow[k >> 4] + m[i][j];
            size_t idx = ((size_t)l * DIMV + o) * DIMV + k;
            __nv_bfloat16 h = __float2bfloat16(wv);
            Whi[idx] = h;
            Wlo[idx] = __float2bfloat16(wv - __bfloat162float(h));
        }
    }
}

__global__ __launch_bounds__(256) void split_x_kernel(
    const float* __restrict__ x, __nv_bfloat16* __restrict__ hi,
    __nv_bfloat16* __restrict__ lo)
{
    size_t i = (size_t)blockIdx.x * 256 + threadIdx.x;
    float v = x[i];
    __nv_bfloat16 h = __float2bfloat16(v);
    hi[i] = h;
    lo[i] = __float2bfloat16(v - __bfloat162float(h));
}

// ---------------------------------------------------------------------------
// GEMM: C[BV,DIMV] = X @ W^T. grid (8, 256), 256 threads, 8 warps (2x4),
// warp tile 64x32. 4-stage ring over K=16 chunks, produce-ahead-2, 2 CTAs/SM.
// Sync: warp 0 polls full[s] (acquire), __syncthreads broadcasts readiness.
// Empty barrier eliminated (reuse distance 4 > 2 intervening CTA barriers).
// mode 0: out = relu(acc+bias) -> bf16 hi/lo pair
// mode 1: out = acc+bias+res -> fp32 (res = hinf fp32 or hi+lo bf16 pair)
// ---------------------------------------------------------------------------
__global__ __launch_bounds__(NTHR, 2) void gemm_kernel(
    const __nv_bfloat16* __restrict__ Xhi, const __nv_bfloat16* __restrict__ Xlo,
    const __nv_bfloat16* __restrict__ Whi, const __nv_bfloat16* __restrict__ Wlo,
    const float* __restrict__ bias, int mode,
    const float* __restrict__ hinf,
    const __nv_bfloat16* __restrict__ hinh, const __nv_bfloat16* __restrict__ hinl,
    float* __restrict__ fout,
    __nv_bfloat16* __restrict__ Ohi, __nv_bfloat16* __restrict__ Olo)
{
    extern __shared__ __align__(128) char smem[];
    const uint32_t sb = (uint32_t)__cvta_generic_to_shared(smem);

    const int tid = threadIdx.x, warp = tid >> 5, lane = tid & 31;
    const int wm = warp >> 2, wn = warp & 3;         // 2 x 4 warp grid, 64x32 tile
    const int m0 = blockIdx.y * TM, n0 = blockIdx.x * TN;

    // barriers: full[s] at MB_BASE + s*16 (one noinc-arrive per thread)
    if (tid == 0) {
#pragma unroll
        for (int s = 0; s < NSTAGE; s++)
            mbar_init(sb + MB_BASE + s * 16, NTHR);
    }
    __syncthreads();

    // producer per-thread layout (hoisted out of chunk loop)
    const int prow = tid >> 1, pseg = tid & 1;
    const uint32_t poff = (uint32_t)(prow * ROWB + pseg * 16);
    const __nv_bfloat16* pXh = Xhi + (size_t)(m0 + prow) * DIMV + pseg * 8;
    const __nv_bfloat16* pXl = Xlo + (size_t)(m0 + prow) * DIMV + pseg * 8;
    const __nv_bfloat16* pWh = Whi + (size_t)(n0 + prow) * DIMV + pseg * 8;
    const __nv_bfloat16* pWl = Wlo + (size_t)(n0 + prow) * DIMV + pseg * 8;

    // ldmatrix per-lane addressing (bytes, relative to stage base)
    const int mi = lane >> 3, rr = lane & 7;
    const uint32_t a_base = (uint32_t)((wm * 64 + (mi & 1) * 8 + rr) * ROWB
                                       + ((mi >> 1) * 8) * 2);
    const uint32_t b_base = (uint32_t)((wn * 32 + ((lane >> 4) << 3) + (lane & 7)) * ROWB
                                       + (((lane >> 3) & 1) * 8) * 2);

#define PRODUCE(sidx, cidx)                                                    \
    do {                                                                       \
        const uint32_t _st = sb + (uint32_t)(sidx) * STAGE_BYTES;              \
        const int _k = (cidx) * KC16;                                          \
        cpa16(_st + OFF_AHI + poff, pXh + _k);                                 \
        cpa16(_st + OFF_ALO + poff, pXl + _k);                                 \
        cpa16(_st + OFF_BHI + poff, pWh + _k);                                 \
        cpa16(_st + OFF_BLO + poff, pWl + _k);                                 \
        cp_arrive_noinc(sb + MB_BASE + (uint32_t)(sidx) * 16);                 \
    } while (0)

    // prologue: produce chunks 0,1 into stages 0,1 (produce-ahead distance 2)
    PRODUCE(0, 0);
    PRODUCE(1, 1);

    float acc[4][4][4];
#pragma unroll
    for (int i = 0; i < 4; i++)
#pragma unroll
        for (int j = 0; j < 4; j++)
#pragma unroll
            for (int q = 0; q < 4; q++) acc[i][j][q] = 0.f;

#pragma unroll 4
    for (int c = 0; c < NC; ++c) {
        const int s = c & 3, j = c >> 2;

        // leader polls readiness of chunk c; CTA barrier broadcasts it.
        if (warp == 0)
            mbar_wait(sb + MB_BASE + (uint32_t)s * 16, j & 1);
        __syncthreads();

        // produce chunk c+2 into stage (c+2)&3. Safe: that stage's previous
        // content (chunk c-2) was consumed before the barrier 2 chunks ago.
        const int pc = c + 2;
        if (pc < NC)
            PRODUCE(pc & 3, pc);

        const uint32_t st = sb + (uint32_t)s * STAGE_BYTES;

        // batch 1: hi fragments
        uint32_t wh[8], fxh[4][4];
#pragma unroll
        for (int nfp = 0; nfp < 2; nfp++)
            ldsm4(wh + 4 * nfp, st + OFF_BHI + b_base + (uint32_t)(nfp * 16 * ROWB));
#pragma unroll
        for (int mf = 0; mf < 4; mf++)
            ldsm4(fxh[mf], st + OFF_AHI + a_base + (uint32_t)(mf * 16 * ROWB));

        // pass 1 (hi x hi) overlaps the lo-batch LDSM latency below
#pragma unroll
        for (int mf = 0; mf < 4; mf++)
#pragma unroll
            for (int nf = 0; nf < 4; nf++)
                mma16816(acc[mf][nf], fxh[mf], wh + 2 * nf);

        // batch 2: lo fragments
        uint32_t wl[8], fxl[4][4];
#pragma unroll
        for (int nfp = 0; nfp < 2; nfp++)
            ldsm4(wl + 4 * nfp, st + OFF_BLO + b_base + (uint32_t)(nfp * 16 * ROWB));
#pragma unroll
        for (int mf = 0; mf < 4; mf++)
            ldsm4(fxl[mf], st + OFF_ALO + a_base + (uint32_t)(mf * 16 * ROWB));

        // passes 2 and 3
#pragma unroll
        for (int mf = 0; mf < 4; mf++)
#pragma unroll
            for (int nf = 0; nf < 4; nf++)
                mma16816(acc[mf][nf], fxl[mf], wh + 2 * nf);
#pragma unroll
        for (int mf = 0; mf < 4; mf++)
#pragma unroll
            for (int nf = 0; nf < 4; nf++)
                mma16816(acc[mf][nf], fxh[mf], wl + 2 * nf);
    }
#undef PRODUCE

    // epilogue
#pragma unroll
    for (int mf = 0; mf < 4; mf++) {
#pragma unroll
        for (int nf = 0; nf < 4; nf++) {
            const float* c = acc[mf][nf];
            int row0 = m0 + wm * 64 + mf * 16 + (lane >> 2);
            int row1 = row0 + 8;
            int n = n0 + wn * 32 + nf * 8 + 2 * (lane & 3);
            float bn0 = bias[n], bn1 = bias[n + 1];
            size_t o0 = (size_t)row0 * DIMV + n;
            size_t o1 = (size_t)row1 * DIMV + n;
            if (mode == 0) {
                float v00 = fmaxf(c[0] + bn0, 0.f), v01 = fmaxf(c[1] + bn1, 0.f);
                float v10 = fmaxf(c[2] + bn0, 0.f), v11 = fmaxf(c[3] + bn1, 0.f);
                __nv_bfloat162 h2, l2;
                h2.x = __float2bfloat16(v00); l2.x = __float2bfloat16(v00 - __bfloat162float(h2.x));
                h2.y = __float2bfloat16(v01); l2.y = __float2bfloat16(v01 - __bfloat162float(h2.y));
                *(__nv_bfloat162*)(Ohi + o0) = h2;
                *(__nv_bfloat162*)(Olo + o0) = l2;
                h2.x = __float2bfloat16(v10); l2.x = __float2bfloat16(v10 - __bfloat162float(h2.x));
                h2.y = __float2bfloat16(v11); l2.y = __float2bfloat16(v11 - __bfloat162float(h2.y));
                *(__nv_bfloat162*)(Ohi + o1) = h2;
                *(__nv_bfloat162*)(Olo + o1) = l2;
            } else {
                float2 hv0, hv1;
                if (hinf) {
                    hv0 = *(const float2*)(hinf + o0);
                    hv1 = *(const float2*)(hinf + o1);
                } else {
                    __nv_bfloat162 h0 = *(const __nv_bfloat162*)(hinh + o0);
                    __nv_bfloat162 l0 = *(const __nv_bfloat162*)(hinl + o0);
                    __nv_bfloat162 h1 = *(const __nv_bfloat162*)(hinh + o1);
                    __nv_bfloat162 l1 = *(const __nv_bfloat162*)(hinl + o1);
                    hv0.x = __bfloat162float(h0.x) + __bfloat162float(l0.x);
                    hv0.y = __bfloat162float(h0.y) + __bfloat162float(l0.y);
                    hv1.x = __bfloat162float(h1.x) + __bfloat162float(l1.x);
                    hv1.y = __bfloat162float(h1.y) + __bfloat162float(l1.y);
                }
                float2 r0v; r0v.x = c[0] + bn0 + hv0.x; r0v.y = c[1] + bn1 + hv0.y;
                float2 r1v; r1v.x = c[2] + bn0 + hv1.x; r1v.y = c[3] + bn1 + hv1.y;
                *(float2*)(fout + o0) = r0v;
                *(float2*)(fout + o1) = r1v;
            }
        }
    }
}

// ---------------------------------------------------------------------------
// LayerNorm: reads fp32 t, writes ONLY the bf16 hi/lo pair.
// ---------------------------------------------------------------------------
__global__ __launch_bounds__(256) void ln_kernel(
    const float* __restrict__ t, const float* __restrict__ g,
    const float* __restrict__ bb,
    __nv_bfloat16* __restrict__ Ohi, __nv_bfloat16* __restrict__ Olo)
{
    int row = blockIdx.x;
    int tid = threadIdx.x;
    const float* tr = t + (size_t)row * DIMV;

    float v[4];
#pragma unroll
    for (int i = 0; i < 4; i++) v[i] = tr[tid + 256 * i];

    float s = v[0] + v[1] + v[2] + v[3];
#pragma unroll
    for (int o = 16; o > 0; o >>= 1) s += __shfl_xor_sync(0xffffffffu, s, o);

    __shared__ float red[8];
    int w = tid >> 5, ln = tid & 31;
    if (ln == 0) red[w] = s;
    __syncthreads();
    float tot = 0.f;
#pragma unroll
    for (int i = 0; i < 8; i++) tot += red[i];
    float mu = tot * (1.0f / 1024.0f);

    float sq = 0.f;
#pragma unroll
    for (int i = 0; i < 4; i++) { float d = v[i] - mu; sq += d * d; }
#pragma unroll
    for (int o = 16; o > 0; o >>= 1) sq += __shfl_xor_sync(0xffffffffu, sq, o);
    __syncthreads();
    if (ln == 0) red[w] = sq;
    __syncthreads();
    float vtot = 0.f;
#pragma unroll
    for (int i = 0; i < 8; i++) vtot += red[i];
    float rs = rsqrtf(vtot * (1.0f / 1024.0f) + 1e-5f);

#pragma unroll
    for (int i = 0; i < 4; i++) {
        int col = tid + 256 * i;
        float o = (v[i] - mu) * rs * g[col] + bb[col];
        size_t idx = (size_t)row * DIMV + col;
        __nv_bfloat16 h = __float2bfloat16(o);
        Ohi[idx] = h;
        Olo[idx] = __float2bfloat16(o - __bfloat162float(h));
    }
}

// ---------------------------------------------------------------------------
// Host
// ---------------------------------------------------------------------------
extern "C" void kernel_launch(void* const* d_in, const int* in_sizes, int n_in,
                              void* d_out, int out_size)
{
    const float* x      = (const float*)d_in[0];
    const int*   qw     = (const int*)d_in[1];
    const float* scales = (const float*)d_in[2];
    const float* bias   = (const float*)d_in[3];
    const float* la     = (const float*)d_in[4];
    const float* lb     = (const float*)d_in[5];
    const float* lng    = (const float*)d_in[6];
    const float* lnb    = (const float*)d_in[7];
    float* out = (float*)d_out;

    void* p;
    cudaGetSymbolAddress(&p, g_Whi);  __nv_bfloat16* Whi  = (__nv_bfloat16*)p;
    cudaGetSymbolAddress(&p, g_Wlo);  __nv_bfloat16* Wlo  = (__nv_bfloat16*)p;
    cudaGetSymbolAddress(&p, g_ahi0); __nv_bfloat16* Ahi0 = (__nv_bfloat16*)p;
    cudaGetSymbolAddress(&p, g_alo0); __nv_bfloat16* Alo0 = (__nv_bfloat16*)p;
    cudaGetSymbolAddress(&p, g_ahi1); __nv_bfloat16* Ahi1 = (__nv_bfloat16*)p;
    cudaGetSymbolAddress(&p, g_alo1); __nv_bfloat16* Alo1 = (__nv_bfloat16*)p;
    cudaGetSymbolAddress(&p, g_ybuf); float* Ybuf = (float*)p;
    cudaGetSymbolAddress(&p, g_h);
    __nv_bfloat16* Hhi = (__nv_bfloat16*)p;
    __nv_bfloat16* Hlo = (__nv_bfloat16*)p + (size_t)BV * DIMV;

    cudaFuncSetAttribute(gemm_kernel,
                         cudaFuncAttributeMaxDynamicSharedMemorySize, SMEM_TOTAL);

    prep_w_kernel<<<dim3(16, 16, NL), 256>>>(qw, scales, la, lb, Whi, Wlo);
    split_x_kernel<<<(BV * DIMV) / 256, 256>>>(x, Hhi, Hlo);

    for (int l = 0; l < NL; l++) {
        const __nv_bfloat16* wh = Whi + (size_t)l * DIMV * DIMV;
        const __nv_bfloat16* wl = Wlo + (size_t)l * DIMV * DIMV;
        const float* bl = bias + (size_t)l * DIMV;
        const int j = l % 3;

        const __nv_bfloat16* xhi = (j == 0) ? Hhi : (j == 1 ? Ahi0 : Ahi1);
        const __nv_bfloat16* xlo = (j == 0) ? Hlo : (j == 1 ? Alo0 : Alo1);

        if (j != 2) {
            __nv_bfloat16* ohi = (j == 0) ? Ahi0 : Ahi1;
            __nv_bfloat16* olo = (j == 0) ? Alo0 : Alo1;
            gemm_kernel<<<dim3(DIMV / TN, BV / TM), NTHR, SMEM_TOTAL>>>(
                xhi, xlo, wh, wl, bl, 0,
                nullptr, nullptr, nullptr, nullptr, ohi, olo);
        } else {
            const float* hinf = (l == 2) ? x : nullptr;
            const __nv_bfloat16* hinh = (l == 2) ? nullptr : Hhi;
            const __nv_bfloat16* hinl = (l == 2) ? nullptr : Hlo;
            float* fo = (l == NL - 1) ? out : Ybuf;
            gemm_kernel<<<dim3(DIMV / TN, BV / TM), NTHR, SMEM_TOTAL>>>(
                xhi, xlo, wh, wl, bl, 1,
                hinf, hinh, hinl, fo, nullptr, nullptr);
            if (l != NL - 1) {
                int blk = l / 3;
                ln_kernel<<<BV, 256>>>(Ybuf, lng + (size_t)blk * DIMV,
                                       lnb + (size_t)blk * DIMV, Hhi, Hlo);
            }
        }
    }
}

// round 17
// speedup vs baseline: 2.8039x; 1.2819x over previous
#include <cuda_runtime.h>
#include <cuda_bf16.h>
#include <cstdint>
#include <cstddef>

// ---------------------------------------------------------------------------
// QLoRABigNet, mma.sync bf16 path. CHAMPION (R12) GEMM restored verbatim:
// K16 x 4-stage mbarrier ring, produce-ahead-2, distributed per-warp waits,
// CTA 128x128, 2 CTAs/SM. (R13 int8, R14 swizzle, R16 leader-poll all
// regressed -> this geometry is the measured local optimum, 510.8us/layer.)
// R17: aux kernels (ln/split) vectorized float4/bf162 -- GEMM untouched.
// ---------------------------------------------------------------------------

#define NL    18
#define DIMV  1024
#define BV    32768
#define NGRP  64

#define TM 128
#define TN 128
#define KC16 16
#define NC (DIMV / KC16)         // 64 chunks
#define NSTAGE 4
#define NTHR 256

#define ROWB 48                  // 32B data + 16B pad, conflict-free ldsm
#define OFF_AHI 0
#define OFF_ALO 6144             // 128*48
#define OFF_BHI 12288
#define OFF_BLO 18432
#define STAGE_BYTES 24576
#define MB_BASE (NSTAGE * STAGE_BYTES)      // 98304
#define SMEM_TOTAL (MB_BASE + 128)          // 98432 -> 2 CTAs/SM

// ---- scratch (device globals: allocation-free contract) --------------------
__device__ __nv_bfloat16 g_Whi[(size_t)NL * DIMV * DIMV];
__device__ __nv_bfloat16 g_Wlo[(size_t)NL * DIMV * DIMV];
__device__ __nv_bfloat16 g_ahi0[(size_t)BV * DIMV];
__device__ __nv_bfloat16 g_alo0[(size_t)BV * DIMV];
__device__ __nv_bfloat16 g_ahi1[(size_t)BV * DIMV];
__device__ __nv_bfloat16 g_alo1[(size_t)BV * DIMV];
__device__ float         g_ybuf[(size_t)BV * DIMV];
__device__ float         g_h[(size_t)BV * DIMV];   // carved: Hhi | Hlo (bf16)

// ---------------------------------------------------------------------------
// PTX helpers
// ---------------------------------------------------------------------------
__device__ __forceinline__ void ldsm4(uint32_t* r, uint32_t a) {
    asm volatile("ldmatrix.sync.aligned.m8n8.x4.shared.b16 {%0,%1,%2,%3}, [%4];\n"
                 : "=r"(r[0]), "=r"(r[1]), "=r"(r[2]), "=r"(r[3]) : "r"(a));
}
__device__ __forceinline__ void mma16816(float* c, const uint32_t* a, const uint32_t* b) {
    asm volatile(
        "mma.sync.aligned.m16n8k16.row.col.f32.bf16.bf16.f32 "
        "{%0,%1,%2,%3}, {%4,%5,%6,%7}, {%8,%9}, {%0,%1,%2,%3};\n"
        : "+f"(c[0]), "+f"(c[1]), "+f"(c[2]), "+f"(c[3])
        : "r"(a[0]), "r"(a[1]), "r"(a[2]), "r"(a[3]), "r"(b[0]), "r"(b[1]));
}
__device__ __forceinline__ void cpa16(uint32_t dst, const void* src) {
    asm volatile("cp.async.cg.shared.global [%0], [%1], 16;" :: "r"(dst), "l"(src));
}
__device__ __forceinline__ void mbar_init(uint32_t addr, uint32_t cnt) {
    asm volatile("mbarrier.init.shared.b64 [%0], %1;" :: "r"(addr), "r"(cnt) : "memory");
}
__device__ __forceinline__ void mbar_arrive(uint32_t addr) {
    asm volatile("mbarrier.arrive.shared.b64 _, [%0];" :: "r"(addr) : "memory");
}
__device__ __forceinline__ void cp_arrive_noinc(uint32_t addr) {
    asm volatile("cp.async.mbarrier.arrive.noinc.shared.b64 [%0];" :: "r"(addr) : "memory");
}
__device__ __forceinline__ void mbar_wait(uint32_t addr, uint32_t parity) {
    asm volatile(
        "{\n .reg .pred P;\n"
        "W%=:\n mbarrier.try_wait.parity.acquire.cta.shared::cta.b64 P, [%0], %1, 0x989680;\n"
        " @P bra D%=;\n bra W%=;\nD%=:\n}"
        :: "r"(addr), "r"(parity) : "memory");
}
__device__ __forceinline__ void mbar_wait_relaxed(uint32_t addr, uint32_t parity) {
    asm volatile(
        "{\n .reg .pred P;\n"
        "W%=:\n mbarrier.try_wait.parity.relaxed.cta.shared::cta.b64 P, [%0], %1, 0x989680;\n"
        " @P bra D%=;\n bra W%=;\nD%=:\n}"
        :: "r"(addr), "r"(parity) : "memory");
}

// ---------------------------------------------------------------------------
// Prepass: W_eff = qw*scale + B@A, split bf16 hi/lo. (validated R3/R5-R12)
// ---------------------------------------------------------------------------
__global__ __launch_bounds__(256) void prep_w_kernel(
    const int* __restrict__ qw, const float* __restrict__ sc,
    const float* __restrict__ la, const float* __restrict__ lb,
    __nv_bfloat16* __restrict__ Whi, __nv_bfloat16* __restrict__ Wlo)
{
    int l  = blockIdx.z;
    int o0 = blockIdx.y * 64;
    int k0 = blockIdx.x * 64;
    int tid = threadIdx.x;

    __shared__ float sLb[64][32];
    __shared__ float sLa[32][64];

    const float* lbp = lb + (size_t)l * DIMV * 32;
    const float* lap = la + (size_t)l * 32 * DIMV;

#pragma unroll
    for (int i = 0; i < 8; i++) {
        int off = tid + i * 256;
        int o = off >> 5, r = off & 31;
        sLb[o][r] = lbp[(size_t)(o0 + o) * 32 + r];
        int r2 = off >> 6, k = off & 63;
        sLa[r2][k] = lap[(size_t)r2 * DIMV + k0 + k];
    }
    __syncthreads();

    int to = tid >> 4, tk = tid & 15;
    float m[4][4];
#pragma unroll
    for (int i = 0; i < 4; i++)
#pragma unroll
        for (int j = 0; j < 4; j++) m[i][j] = 0.f;

#pragma unroll 8
    for (int r = 0; r < 32; r++) {
        float av[4], bv[4];
#pragma unroll
        for (int j = 0; j < 4; j++) av[j] = sLa[r][tk * 4 + j];
#pragma unroll
        for (int i = 0; i < 4; i++) bv[i] = sLb[to * 4 + i][r];
#pragma unroll
        for (int i = 0; i < 4; i++)
#pragma unroll
            for (int j = 0; j < 4; j++) m[i][j] += bv[i] * av[j];
    }

#pragma unroll
    for (int i = 0; i < 4; i++) {
        int o = o0 + to * 4 + i;
        const int*   qrow = qw + ((size_t)l * DIMV + o) * DIMV + k0;
        const float* srow = sc + ((size_t)l * DIMV + o) * NGRP;
#pragma unroll
        for (int j = 0; j < 4; j++) {
            int k = k0 + tk * 4 + j;
            float wv = (float)qrow[tk * 4 + j] * srow[k >> 4] + m[i][j];
            size_t idx = ((size_t)l * DIMV + o) * DIMV + k;
            __nv_bfloat16 h = __float2bfloat16(wv);
            Whi[idx] = h;
            Wlo[idx] = __float2bfloat16(wv - __bfloat162float(h));
        }
    }
}

// vectorized: each thread handles 4 contiguous elems (16B load, 2x bf162 store)
__global__ __launch_bounds__(256) void split_x_kernel(
    const float* __restrict__ x, __nv_bfloat16* __restrict__ hi,
    __nv_bfloat16* __restrict__ lo)
{
    size_t i4 = (size_t)blockIdx.x * 256 + threadIdx.x;
    float4 v = *(const float4*)(x + i4 * 4);
    __nv_bfloat162 h0, h1, l0, l1;
    h0.x = __float2bfloat16(v.x); l0.x = __float2bfloat16(v.x - __bfloat162float(h0.x));
    h0.y = __float2bfloat16(v.y); l0.y = __float2bfloat16(v.y - __bfloat162float(h0.y));
    h1.x = __float2bfloat16(v.z); l1.x = __float2bfloat16(v.z - __bfloat162float(h1.x));
    h1.y = __float2bfloat16(v.w); l1.y = __float2bfloat16(v.w - __bfloat162float(h1.y));
    *(__nv_bfloat162*)(hi + i4 * 4)     = h0;
    *(__nv_bfloat162*)(hi + i4 * 4 + 2) = h1;
    *(__nv_bfloat162*)(lo + i4 * 4)     = l0;
    *(__nv_bfloat162*)(lo + i4 * 4 + 2) = l1;
}

// ---------------------------------------------------------------------------
// GEMM (CHAMPION R12, verbatim): grid (8, 256), 256 threads, 8 warps (2x4),
// warp tile 64x32, mbarrier 4-stage ring over K=16 chunks, 2 CTAs/SM.
// mode 0: out = relu(acc+bias) -> bf16 hi/lo pair
// mode 1: out = acc+bias+res -> fp32 (res = hinf fp32 or hi+lo bf16 pair)
// ---------------------------------------------------------------------------
__global__ __launch_bounds__(NTHR, 2) void gemm_kernel(
    const __nv_bfloat16* __restrict__ Xhi, const __nv_bfloat16* __restrict__ Xlo,
    const __nv_bfloat16* __restrict__ Whi, const __nv_bfloat16* __restrict__ Wlo,
    const float* __restrict__ bias, int mode,
    const float* __restrict__ hinf,
    const __nv_bfloat16* __restrict__ hinh, const __nv_bfloat16* __restrict__ hinl,
    float* __restrict__ fout,
    __nv_bfloat16* __restrict__ Ohi, __nv_bfloat16* __restrict__ Olo)
{
    extern __shared__ __align__(128) char smem[];
    const uint32_t sb = (uint32_t)__cvta_generic_to_shared(smem);

    const int tid = threadIdx.x, warp = tid >> 5, lane = tid & 31;
    const int wm = warp >> 2, wn = warp & 3;         // 2 x 4 warp grid, 64x32 tile
    const int m0 = blockIdx.y * TM, n0 = blockIdx.x * TN;

    // barriers: full[s] at MB_BASE + s*16, empty[s] at +8
    if (tid == 0) {
#pragma unroll
        for (int s = 0; s < NSTAGE; s++) {
            mbar_init(sb + MB_BASE + s * 16, NTHR);  // full: one noinc-arrive per thread
            mbar_init(sb + MB_BASE + s * 16 + 8, 8); // empty: one arrive per warp
        }
    }
    __syncthreads();

    // producer per-thread layout (hoisted out of chunk loop)
    const int prow = tid >> 1, pseg = tid & 1;
    const uint32_t poff = (uint32_t)(prow * ROWB + pseg * 16);
    const __nv_bfloat16* pXh = Xhi + (size_t)(m0 + prow) * DIMV + pseg * 8;
    const __nv_bfloat16* pXl = Xlo + (size_t)(m0 + prow) * DIMV + pseg * 8;
    const __nv_bfloat16* pWh = Whi + (size_t)(n0 + prow) * DIMV + pseg * 8;
    const __nv_bfloat16* pWl = Wlo + (size_t)(n0 + prow) * DIMV + pseg * 8;

    // ldmatrix per-lane addressing (bytes, relative to stage base)
    const int mi = lane >> 3, rr = lane & 7;
    const uint32_t a_base = (uint32_t)((wm * 64 + (mi & 1) * 8 + rr) * ROWB
                                       + ((mi >> 1) * 8) * 2);
    const uint32_t b_base = (uint32_t)((wn * 32 + ((lane >> 4) << 3) + (lane & 7)) * ROWB
                                       + (((lane >> 3) & 1) * 8) * 2);

#define PRODUCE(sidx, cidx)                                                    \
    do {                                                                       \
        const uint32_t _st = sb + (uint32_t)(sidx) * STAGE_BYTES;              \
        const int _k = (cidx) * KC16;                                          \
        cpa16(_st + OFF_AHI + poff, pXh + _k);                                 \
        cpa16(_st + OFF_ALO + poff, pXl + _k);                                 \
        cpa16(_st + OFF_BHI + poff, pWh + _k);                                 \
        cpa16(_st + OFF_BLO + poff, pWl + _k);                                 \
        cp_arrive_noinc(sb + MB_BASE + (uint32_t)(sidx) * 16);                 \
    } while (0)

    // prologue: produce chunks 0,1 into stages 0,1 (produce-ahead distance 2)
    PRODUCE(0, 0);
    PRODUCE(1, 1);

    float acc[4][4][4];
#pragma unroll
    for (int i = 0; i < 4; i++)
#pragma unroll
        for (int j = 0; j < 4; j++)
#pragma unroll
            for (int q = 0; q < 4; q++) acc[i][j][q] = 0.f;

#pragma unroll 4
    for (int c = 0; c < NC; ++c) {
        // produce chunk c+2 (stage (c+2)%4): WAR-gated on consumption of c-2
        const int pc = c + 2;
        if (pc < NC) {
            const int ps = pc & 3, pj = pc >> 2;
            if (pj > 0)
                mbar_wait_relaxed(sb + MB_BASE + (uint32_t)ps * 16 + 8, (pj - 1) & 1);
            PRODUCE(ps, pc);
        }

        // consume chunk c
        const int s = c & 3, j = c >> 2;
        mbar_wait(sb + MB_BASE + (uint32_t)s * 16, j & 1);
        const uint32_t st = sb + (uint32_t)s * STAGE_BYTES;

        // batch 1: hi fragments
        uint32_t wh[8], fxh[4][4];
#pragma unroll
        for (int nfp = 0; nfp < 2; nfp++)
            ldsm4(wh + 4 * nfp, st + OFF_BHI + b_base + (uint32_t)(nfp * 16 * ROWB));
#pragma unroll
        for (int mf = 0; mf < 4; mf++)
            ldsm4(fxh[mf], st + OFF_AHI + a_base + (uint32_t)(mf * 16 * ROWB));

        // pass 1 (hi x hi) overlaps the lo-batch LDSM latency below
#pragma unroll
        for (int mf = 0; mf < 4; mf++)
#pragma unroll
            for (int nf = 0; nf < 4; nf++)
                mma16816(acc[mf][nf], fxh[mf], wh + 2 * nf);

        // batch 2: lo fragments
        uint32_t wl[8], fxl[4][4];
#pragma unroll
        for (int nfp = 0; nfp < 2; nfp++)
            ldsm4(wl + 4 * nfp, st + OFF_BLO + b_base + (uint32_t)(nfp * 16 * ROWB));
#pragma unroll
        for (int mf = 0; mf < 4; mf++)
            ldsm4(fxl[mf], st + OFF_ALO + a_base + (uint32_t)(mf * 16 * ROWB));

        // buffer free for refill once all fragments are in registers
        if (lane == 0)
            mbar_arrive(sb + MB_BASE + (uint32_t)s * 16 + 8);

        // passes 2 and 3
#pragma unroll
        for (int mf = 0; mf < 4; mf++)
#pragma unroll
            for (int nf = 0; nf < 4; nf++)
                mma16816(acc[mf][nf], fxl[mf], wh + 2 * nf);
#pragma unroll
        for (int mf = 0; mf < 4; mf++)
#pragma unroll
            for (int nf = 0; nf < 4; nf++)
                mma16816(acc[mf][nf], fxh[mf], wl + 2 * nf);
    }
#undef PRODUCE

    // epilogue
#pragma unroll
    for (int mf = 0; mf < 4; mf++) {
#pragma unroll
        for (int nf = 0; nf < 4; nf++) {
            const float* c = acc[mf][nf];
            int row0 = m0 + wm * 64 + mf * 16 + (lane >> 2);
            int row1 = row0 + 8;
            int n = n0 + wn * 32 + nf * 8 + 2 * (lane & 3);
            float bn0 = bias[n], bn1 = bias[n + 1];
            size_t o0 = (size_t)row0 * DIMV + n;
            size_t o1 = (size_t)row1 * DIMV + n;
            if (mode == 0) {
                float v00 = fmaxf(c[0] + bn0, 0.f), v01 = fmaxf(c[1] + bn1, 0.f);
                float v10 = fmaxf(c[2] + bn0, 0.f), v11 = fmaxf(c[3] + bn1, 0.f);
                __nv_bfloat162 h2, l2;
                h2.x = __float2bfloat16(v00); l2.x = __float2bfloat16(v00 - __bfloat162float(h2.x));
                h2.y = __float2bfloat16(v01); l2.y = __float2bfloat16(v01 - __bfloat162float(h2.y));
                *(__nv_bfloat162*)(Ohi + o0) = h2;
                *(__nv_bfloat162*)(Olo + o0) = l2;
                h2.x = __float2bfloat16(v10); l2.x = __float2bfloat16(v10 - __bfloat162float(h2.x));
                h2.y = __float2bfloat16(v11); l2.y = __float2bfloat16(v11 - __bfloat162float(h2.y));
                *(__nv_bfloat162*)(Ohi + o1) = h2;
                *(__nv_bfloat162*)(Olo + o1) = l2;
            } else {
                float2 hv0, hv1;
                if (hinf) {
                    hv0 = *(const float2*)(hinf + o0);
                    hv1 = *(const float2*)(hinf + o1);
                } else {
                    __nv_bfloat162 h0 = *(const __nv_bfloat162*)(hinh + o0);
                    __nv_bfloat162 l0 = *(const __nv_bfloat162*)(hinl + o0);
                    __nv_bfloat162 h1 = *(const __nv_bfloat162*)(hinh + o1);
                    __nv_bfloat162 l1 = *(const __nv_bfloat162*)(hinl + o1);
                    hv0.x = __bfloat162float(h0.x) + __bfloat162float(l0.x);
                    hv0.y = __bfloat162float(h0.y) + __bfloat162float(l0.y);
                    hv1.x = __bfloat162float(h1.x) + __bfloat162float(l1.x);
                    hv1.y = __bfloat162float(h1.y) + __bfloat162float(l1.y);
                }
                float2 r0v; r0v.x = c[0] + bn0 + hv0.x; r0v.y = c[1] + bn1 + hv0.y;
                float2 r1v; r1v.x = c[2] + bn0 + hv1.x; r1v.y = c[3] + bn1 + hv1.y;
                *(float2*)(fout + o0) = r0v;
                *(float2*)(fout + o1) = r1v;
            }
        }
    }
}

// ---------------------------------------------------------------------------
// LayerNorm (vectorized): each thread owns 4 contiguous cols (float4 loads,
// bf162 stores). Writes ONLY the bf16 hi/lo pair.
// ---------------------------------------------------------------------------
__global__ __launch_bounds__(256) void ln_kernel(
    const float* __restrict__ t, const float* __restrict__ g,
    const float* __restrict__ bb,
    __nv_bfloat16* __restrict__ Ohi, __nv_bfloat16* __restrict__ Olo)
{
    int row = blockIdx.x;
    int tid = threadIdx.x;
    const float* tr = t + (size_t)row * DIMV;

    float4 v = *(const float4*)(tr + tid * 4);

    float s = v.x + v.y + v.z + v.w;
#pragma unroll
    for (int o = 16; o > 0; o >>= 1) s += __shfl_xor_sync(0xffffffffu, s, o);

    __shared__ float red[8];
    int w = tid >> 5, ln = tid & 31;
    if (ln == 0) red[w] = s;
    __syncthreads();
    float tot = 0.f;
#pragma unroll
    for (int i = 0; i < 8; i++) tot += red[i];
    float mu = tot * (1.0f / 1024.0f);

    float dx = v.x - mu, dy = v.y - mu, dz = v.z - mu, dw = v.w - mu;
    float sq = dx * dx + dy * dy + dz * dz + dw * dw;
#pragma unroll
    for (int o = 16; o > 0; o >>= 1) sq += __shfl_xor_sync(0xffffffffu, sq, o);
    __syncthreads();
    if (ln == 0) red[w] = sq;
    __syncthreads();
    float vtot = 0.f;
#pragma unroll
    for (int i = 0; i < 8; i++) vtot += red[i];
    float rs = rsqrtf(vtot * (1.0f / 1024.0f) + 1e-5f);

    float4 gv = *(const float4*)(g + tid * 4);
    float4 bv = *(const float4*)(bb + tid * 4);
    float o0 = dx * rs * gv.x + bv.x;
    float o1 = dy * rs * gv.y + bv.y;
    float o2 = dz * rs * gv.z + bv.z;
    float o3 = dw * rs * gv.w + bv.w;

    size_t base = (size_t)row * DIMV + tid * 4;
    __nv_bfloat162 h0, h1, l0, l1;
    h0.x = __float2bfloat16(o0); l0.x = __float2bfloat16(o0 - __bfloat162float(h0.x));
    h0.y = __float2bfloat16(o1); l0.y = __float2bfloat16(o1 - __bfloat162float(h0.y));
    h1.x = __float2bfloat16(o2); l1.x = __float2bfloat16(o2 - __bfloat162float(h1.x));
    h1.y = __float2bfloat16(o3); l1.y = __float2bfloat16(o3 - __bfloat162float(h1.y));
    *(__nv_bfloat162*)(Ohi + base)     = h0;
    *(__nv_bfloat162*)(Ohi + base + 2) = h1;
    *(__nv_bfloat162*)(Olo + base)     = l0;
    *(__nv_bfloat162*)(Olo + base + 2) = l1;
}

// ---------------------------------------------------------------------------
// Host
// ---------------------------------------------------------------------------
extern "C" void kernel_launch(void* const* d_in, const int* in_sizes, int n_in,
                              void* d_out, int out_size)
{
    const float* x      = (const float*)d_in[0];
    const int*   qw     = (const int*)d_in[1];
    const float* scales = (const float*)d_in[2];
    const float* bias   = (const float*)d_in[3];
    const float* la     = (const float*)d_in[4];
    const float* lb     = (const float*)d_in[5];
    const float* lng    = (const float*)d_in[6];
    const float* lnb    = (const float*)d_in[7];
    float* out = (float*)d_out;

    void* p;
    cudaGetSymbolAddress(&p, g_Whi);  __nv_bfloat16* Whi  = (__nv_bfloat16*)p;
    cudaGetSymbolAddress(&p, g_Wlo);  __nv_bfloat16* Wlo  = (__nv_bfloat16*)p;
    cudaGetSymbolAddress(&p, g_ahi0); __nv_bfloat16* Ahi0 = (__nv_bfloat16*)p;
    cudaGetSymbolAddress(&p, g_alo0); __nv_bfloat16* Alo0 = (__nv_bfloat16*)p;
    cudaGetSymbolAddress(&p, g_ahi1); __nv_bfloat16* Ahi1 = (__nv_bfloat16*)p;
    cudaGetSymbolAddress(&p, g_alo1); __nv_bfloat16* Alo1 = (__nv_bfloat16*)p;
    cudaGetSymbolAddress(&p, g_ybuf); float* Ybuf = (float*)p;
    cudaGetSymbolAddress(&p, g_h);
    __nv_bfloat16* Hhi = (__nv_bfloat16*)p;
    __nv_bfloat16* Hlo = (__nv_bfloat16*)p + (size_t)BV * DIMV;

    cudaFuncSetAttribute(gemm_kernel,
                         cudaFuncAttributeMaxDynamicSharedMemorySize, SMEM_TOTAL);

    prep_w_kernel<<<dim3(16, 16, NL), 256>>>(qw, scales, la, lb, Whi, Wlo);
    split_x_kernel<<<(BV * DIMV) / 1024, 256>>>(x, Hhi, Hlo);

    for (int l = 0; l < NL; l++) {
        const __nv_bfloat16* wh = Whi + (size_t)l * DIMV * DIMV;
        const __nv_bfloat16* wl = Wlo + (size_t)l * DIMV * DIMV;
        const float* bl = bias + (size_t)l * DIMV;
        const int j = l % 3;

        const __nv_bfloat16* xhi = (j == 0) ? Hhi : (j == 1 ? Ahi0 : Ahi1);
        const __nv_bfloat16* xlo = (j == 0) ? Hlo : (j == 1 ? Alo0 : Alo1);

        if (j != 2) {
            __nv_bfloat16* ohi = (j == 0) ? Ahi0 : Ahi1;
            __nv_bfloat16* olo = (j == 0) ? Alo0 : Alo1;
            gemm_kernel<<<dim3(DIMV / TN, BV / TM), NTHR, SMEM_TOTAL>>>(
                xhi, xlo, wh, wl, bl, 0,
                nullptr, nullptr, nullptr, nullptr, ohi, olo);
        } else {
            const float* hinf = (l == 2) ? x : nullptr;
            const __nv_bfloat16* hinh = (l == 2) ? nullptr : Hhi;
            const __nv_bfloat16* hinl = (l == 2) ? nullptr : Hlo;
            float* fo = (l == NL - 1) ? out : Ybuf;
            gemm_kernel<<<dim3(DIMV / TN, BV / TM), NTHR, SMEM_TOTAL>>>(
                xhi, xlo, wh, wl, bl, 1,
                hinf, hinh, hinl, fo, nullptr, nullptr);
            if (l != NL - 1) {
                int blk = l / 3;
                ln_kernel<<<BV, 256>>>(Ybuf, lng + (size_t)blk * DIMV,
                                       lnb + (size_t)blk * DIMV, Hhi, Hlo);
            }
        }
    }
}